// round 4
// baseline (speedup 1.0000x reference)
#include <cuda_runtime.h>
#include <cuda_bf16.h>

// YOLO post-process:
//   in : (16, 25200, 85) f32 rows = [x, y, w, h, conf, cls0..cls79]
//   out: (16, 25200, 6)  f32 rows = [x-w/2, y-h/2, x+w/2, y+h/2, conf*max(cls), argmax(cls)]
//        zeroed where conf*max(cls) <= 0.25
//
// R4: L1TEX-wavefront minimization. R2/R3 burned ~1400 wavefronts per 64 rows
// (8 row-lines per LDG.32, or conflicted LDS). Now:
//   - stage 256 rows (87KB) per block via coalesced LDG.128 + STS.128
//     (bytes/128 wavefronts each),
//   - compute with ONE THREAD PER ROW: scalar LDS at row stride 85 floats
//     -> bank stride 21, gcd(21,32)=1 -> all 32 lanes on distinct banks:
//     conflict-free, bytes/128 wavefronts.
// Total ~3*bytes/128 ~= 2040 wf per 256 rows (vs 5632 equivalent in R2),
// pushing the kernel from L1-bound (~33us) to the DRAM floor (~21-25us).

static constexpr int   ROWLEN       = 85;
static constexpr int   OUTLEN       = 6;
static constexpr int   THREADS      = 256;
static constexpr int   ROWS_PER_BLK = 256;                       // 1 thread : 1 row
static constexpr int   TILE_FLOATS  = ROWS_PER_BLK * ROWLEN;     // 21760
static constexpr int   TILE_F4      = TILE_FLOATS / 4;           // 5440
static constexpr int   F4_PER_THR   = TILE_F4 / THREADS;         // 21 (+64 tail)
static constexpr int   F4_TAIL      = TILE_F4 - F4_PER_THR * THREADS; // 64
static constexpr int   SMEM_BYTES   = (TILE_FLOATS + ROWS_PER_BLK * OUTLEN) * 4; // 93184
static constexpr float CONF_THRESH  = 0.25f;
static constexpr float NEG_INF      = -1e30f;

__global__ __launch_bounds__(THREADS)
void yolo_post_kernel(const float4* __restrict__ in4,
                      float* __restrict__ out,
                      int nrows)
{
    extern __shared__ float smem[];
    float* tile  = smem;                  // [TILE_FLOATS] raw row-major
    float* s_out = smem + TILE_FLOATS;    // [ROWS_PER_BLK * OUTLEN]

    const int tid = threadIdx.x;

    // ---- Stage tile: coalesced LDG.128 -> STS.128, batched 7-deep for MLP ----
    {
        const size_t base4 = (size_t)blockIdx.x * TILE_F4;
        #pragma unroll
        for (int grp = 0; grp < F4_PER_THR / 7; grp++) {        // 3 groups of 7
            float4 q[7];
            #pragma unroll
            for (int i = 0; i < 7; i++)
                q[i] = in4[base4 + tid + (size_t)(grp * 7 + i) * THREADS];
            #pragma unroll
            for (int i = 0; i < 7; i++)
                *reinterpret_cast<float4*>(&tile[4 * (tid + (grp * 7 + i) * THREADS)]) = q[i];
        }
        if (tid < F4_TAIL) {
            const int t = F4_PER_THR * THREADS + tid;
            *reinterpret_cast<float4*>(&tile[4 * t]) = in4[base4 + t];
        }
    }
    __syncthreads();

    // ---- Compute: one thread per row, conflict-free scalar LDS ----
    const int row = blockIdx.x * ROWS_PER_BLK + tid;
    if (row < nrows) {
        const float* rp = &tile[tid * ROWLEN];

        const float x    = rp[0];
        const float y    = rp[1];
        const float w    = rp[2];
        const float h    = rp[3];
        const float conf = rp[4];

        // 80 classes in 5 chunks of 16 (batched LDS for MLP).
        float m  = NEG_INF;
        int   mi = 0;
        #pragma unroll
        for (int kb = 5; kb < ROWLEN; kb += 16) {
            float c[16];
            #pragma unroll
            for (int i = 0; i < 16; i++)
                c[i] = rp[kb + i];
            #pragma unroll
            for (int i = 0; i < 16; i++)
                if (c[i] > m) { m = c[i]; mi = kb + i - 5; }   // strict '>' = first max
        }

        const float score = conf * m;
        const bool  keep  = score > CONF_THRESH;

        float* srow = &s_out[tid * OUTLEN];
        srow[0] = keep ? fmaf(-0.5f, w, x) : 0.0f;
        srow[1] = keep ? fmaf(-0.5f, h, y) : 0.0f;
        srow[2] = keep ? fmaf( 0.5f, w, x) : 0.0f;
        srow[3] = keep ? fmaf( 0.5f, h, y) : 0.0f;
        srow[4] = keep ? score             : 0.0f;
        srow[5] = keep ? (float)mi         : 0.0f;
    }
    __syncthreads();

    // ---- Contiguous 6144B output store per block ----
    const size_t obase = (size_t)blockIdx.x * (ROWS_PER_BLK * OUTLEN);
    const size_t olim  = (size_t)nrows * OUTLEN;
    #pragma unroll
    for (int s = 0; s < OUTLEN; s++) {
        const int i = tid + s * THREADS;
        if (obase + i < olim)
            out[obase + i] = s_out[i];
    }
}

extern "C" void kernel_launch(void* const* d_in, const int* in_sizes, int n_in,
                              void* d_out, int out_size)
{
    const float4* in4 = (const float4*)d_in[0];
    float*        out = (float*)d_out;

    const int nrows  = out_size / OUTLEN;                            // 403200
    const int blocks = (nrows + ROWS_PER_BLK - 1) / ROWS_PER_BLK;    // 1575

    cudaFuncSetAttribute(yolo_post_kernel,
                         cudaFuncAttributeMaxDynamicSharedMemorySize, SMEM_BYTES);
    yolo_post_kernel<<<blocks, THREADS, SMEM_BYTES>>>(in4, out, nrows);
}